// round 11
// baseline (speedup 1.0000x reference)
#include <cuda_runtime.h>
#include <cuda_fp16.h>
#include <cstdint>

#define BROWS 32768
#define HDIM  512

#define OFF_S2E 0
#define OFF_TF  1310720
#define OFF_FW  3932160
#define OFF_FG  6553600
#define OFF_WG  7864320
#define OFF_HD  9175040
#define WT_TOT  10223616

__device__ __half g_wh[WT_TOT];
__device__ float g_e [BROWS*HDIM];
__device__ float g_f [BROWS*HDIM];
__device__ float g_w [BROWS*HDIM];
__device__ float g_fm[BROWS*HDIM];
__device__ float g_wm[BROWS*HDIM];
__device__ float g_h2[BROWS*HDIM];
__device__ float g_h3[BROWS*HDIM];

// ---------------- helpers ----------------
__device__ __forceinline__ uint32_t smem_u32(const void* p) {
    uint32_t a;
    asm("{ .reg .u64 t; cvta.to.shared.u64 t, %1; cvt.u32.u64 %0, t; }" : "=r"(a) : "l"(p));
    return a;
}
__device__ __forceinline__ void cpa16(uint32_t dst, const void* src) {
    asm volatile("cp.async.cg.shared.global [%0], [%1], 16;" :: "r"(dst), "l"(src));
}
#define CP_COMMIT() asm volatile("cp.async.commit_group;" ::: "memory")
#define CP_WAIT1()  asm volatile("cp.async.wait_group 1;" ::: "memory")
#define CP_WAIT0()  asm volatile("cp.async.wait_group 0;" ::: "memory")

#define LDM4(r, addr) \
    asm volatile("ldmatrix.sync.aligned.m8n8.x4.shared.b16 {%0,%1,%2,%3}, [%4];" \
        : "=r"((r)[0]), "=r"((r)[1]), "=r"((r)[2]), "=r"((r)[3]) : "r"(addr))

#define MMA(d, a, b) \
    asm volatile("mma.sync.aligned.m16n8k16.row.col.f32.f16.f16.f32 " \
        "{%0,%1,%2,%3}, {%4,%5,%6,%7}, {%8,%9}, {%0,%1,%2,%3};" \
        : "+f"((d)[0]), "+f"((d)[1]), "+f"((d)[2]), "+f"((d)[3]) \
        : "r"((a)[0]), "r"((a)[1]), "r"((a)[2]), "r"((a)[3]), "r"((b)[0]), "r"((b)[1]))

// transpose [K,512] fp32 -> [512,K] fp16 (layer = blockIdx.z)
__global__ void prep_kernel(const float* src, __half* dh, int K) {
    __shared__ float tile[32][33];
    int z = blockIdx.z;
    src += (size_t)z * K * 512;
    size_t dof = (size_t)z * 512 * K;
    int k0 = blockIdx.x * 32, n0 = blockIdx.y * 32;
    int tx = threadIdx.x, ty = threadIdx.y;
    for (int r = ty; r < 32; r += 8)
        tile[r][tx] = src[(size_t)(k0 + r) * 512 + n0 + tx];
    __syncthreads();
    for (int r = ty; r < 32; r += 8)
        dh[dof + (size_t)(n0 + r) * K + k0 + tx] = __float2half_rn(tile[tx][r]);
}

// smem byte offsets (dynamic smem)
#define AF0 0
#define AF1 18432
#define AHO 36864
#define BH0 47104
#define BH1 57344
#define SMEM_SZ 67584

// modes: 0 bias  1 bias+add  2 gelu(x+bias)  3 add + sigmoid(x+bias)*(mix-add)
__global__ void __launch_bounds__(256, 2) gemm_kernel(
    const float* A1, const float* A2,
    const __half* Bh, int Ktot,
    const float* bias, int mode, const float* add, const float* mix, float* out)
{
    extern __shared__ char smem[];
    const uint32_t sb = smem_u32(smem);
    const int tid = threadIdx.x, lane = tid & 31, wid = tid >> 5;
    const int m0 = blockIdx.y * 128, n0 = blockIdx.x * 128;
    const int wm = wid & 3, wn = wid >> 2;
    const int rowA = tid >> 1, segA = tid & 1;

    float acc[2][8][4];
    #pragma unroll
    for (int i = 0; i < 2; i++)
        #pragma unroll
        for (int j = 0; j < 8; j++)
            #pragma unroll
            for (int q = 0; q < 4; q++) acc[i][j][q] = 0.f;

    const int NC = Ktot >> 5;

#define ISSUE(cc, buf) do {                                                        \
    int kg_ = (cc) * 32;                                                           \
    const float* Ap_ = (kg_ < 512) ? A1 : A2;                                      \
    int kk_ = (kg_ < 512) ? kg_ : kg_ - 512;                                       \
    const float* as_ = Ap_ + (size_t)(m0 + rowA) * HDIM + kk_ + segA * 16;         \
    uint32_t ad_ = sb + ((buf) ? AF1 : AF0) + rowA * 144 + segA * 64;              \
    cpa16(ad_, as_); cpa16(ad_ + 16, as_ + 4);                                     \
    cpa16(ad_ + 32, as_ + 8); cpa16(ad_ + 48, as_ + 12);                           \
    size_t bo_ = (size_t)(n0 + rowA) * Ktot + kg_ + segA * 16;                     \
    uint32_t bd_ = sb + ((buf) ? BH1 : BH0) + rowA * 80 + segA * 32;               \
    cpa16(bd_, Bh + bo_); cpa16(bd_ + 16, Bh + bo_ + 8);                           \
    CP_COMMIT();                                                                   \
} while (0)

    ISSUE(0, 0);

    // ldmatrix lane addressing
    const int arow = wm * 32 + (lane & 15);
    const int acolb = ((lane >> 4) & 1) * 16;           // byte offset (k half)
    const int g = lane >> 3, lr = lane & 7;
    const int brow = wn * 64 + ((g & 2) ? 8 : 0) + lr;  // n row within tile
    const int bcolb = (g & 1) * 16;

    for (int c = 0; c < NC; c++) {
        __syncthreads();                 // previous compute done on all threads
        if (c + 1 < NC) { ISSUE(c + 1, (c + 1) & 1); CP_WAIT1(); }
        else            { CP_WAIT0(); }

        // convert this thread's own copied A rows: fp32 -> fp16 (hi only)
        {
            const float* af = (const float*)(smem + ((c & 1) ? AF1 : AF0)) + rowA * 36 + segA * 16;
            float4 q0 = *(const float4*)(af + 0);
            float4 q1 = *(const float4*)(af + 4);
            float4 q2 = *(const float4*)(af + 8);
            float4 q3 = *(const float4*)(af + 12);
            uint4 H0, H1;
            __half2 t;
            t = __floats2half2_rn(q0.x, q0.y); H0.x = *(uint32_t*)&t;
            t = __floats2half2_rn(q0.z, q0.w); H0.y = *(uint32_t*)&t;
            t = __floats2half2_rn(q1.x, q1.y); H0.z = *(uint32_t*)&t;
            t = __floats2half2_rn(q1.z, q1.w); H0.w = *(uint32_t*)&t;
            t = __floats2half2_rn(q2.x, q2.y); H1.x = *(uint32_t*)&t;
            t = __floats2half2_rn(q2.z, q2.w); H1.y = *(uint32_t*)&t;
            t = __floats2half2_rn(q3.x, q3.y); H1.z = *(uint32_t*)&t;
            t = __floats2half2_rn(q3.z, q3.w); H1.w = *(uint32_t*)&t;
            char* ah = smem + AHO + rowA * 80 + segA * 32;
            *(uint4*)(ah) = H0; *(uint4*)(ah + 16) = H1;
        }
        __syncthreads();                 // A converted, B(c) visible everywhere

        const uint32_t bhb = sb + ((c & 1) ? BH1 : BH0);
        #pragma unroll
        for (int ks = 0; ks < 2; ks++) {
            uint32_t ah_[2][4];
            #pragma unroll
            for (int i = 0; i < 2; i++) {
                uint32_t ao = (uint32_t)((arow + i * 16) * 80 + ks * 32 + acolb);
                LDM4(ah_[i], sb + AHO + ao);
            }
            #pragma unroll
            for (int jp = 0; jp < 4; jp++) {
                uint32_t bo = (uint32_t)((brow + jp * 16) * 80 + ks * 32 + bcolb);
                uint32_t bh_[4];
                LDM4(bh_, bhb + bo);
                #pragma unroll
                for (int i = 0; i < 2; i++) {
                    #pragma unroll
                    for (int jj = 0; jj < 2; jj++) {
                        MMA(acc[i][jp * 2 + jj], ah_[i], bh_ + 2 * jj);
                    }
                }
            }
        }
    }

    // epilogue: thread owns (rows r0,r0+8) x col pairs, float2 stores
    const int r0b = m0 + wm * 32 + (lane >> 2);
    const int cb  = n0 + wn * 64 + (lane & 3) * 2;
    const float is2 = 0.7071067811865475f;
    #pragma unroll
    for (int i = 0; i < 2; i++) {
        #pragma unroll
        for (int j = 0; j < 8; j++) {
            int cc = cb + j * 8;
            float b0 = bias[cc], b1 = bias[cc + 1];
            #pragma unroll
            for (int h = 0; h < 2; h++) {
                int rr = r0b + i * 16 + h * 8;
                size_t gix = (size_t)rr * HDIM + cc;
                float v0 = acc[i][j][h * 2 + 0] + b0;
                float v1 = acc[i][j][h * 2 + 1] + b1;
                float2 res;
                if (mode == 0) {
                    res.x = v0; res.y = v1;
                } else if (mode == 1) {
                    float2 ad = *(const float2*)(add + gix);
                    res.x = v0 + ad.x; res.y = v1 + ad.y;
                } else if (mode == 2) {
                    res.x = 0.5f * v0 * (1.f + erff(v0 * is2));
                    res.y = 0.5f * v1 * (1.f + erff(v1 * is2));
                } else {
                    float2 ad = *(const float2*)(add + gix);
                    float2 mx = *(const float2*)(mix + gix);
                    float s0 = 1.f / (1.f + __expf(-v0));
                    float s1 = 1.f / (1.f + __expf(-v1));
                    res.x = ad.x + s0 * (mx.x - ad.x);
                    res.y = ad.y + s1 * (mx.y - ad.y);
                }
                *(float2*)(out + gix) = res;
            }
        }
    }
}

// tiny second-layer heads: out[B,7]
__global__ void heads_kernel(
    const float* hs, const float* he, const float* hf, const float* hw,
    const float* Ws, const float* bs, const float* We, const float* be,
    const float* Wf, const float* bfv, const float* Ww, const float* bw,
    float* out)
{
    int gw = (int)((blockIdx.x * blockDim.x + threadIdx.x) >> 5);
    int lane = threadIdx.x & 31;
    if (gw >= BROWS) return;
    size_t base = (size_t)gw * HDIM;
    float a[7] = {0, 0, 0, 0, 0, 0, 0};
    #pragma unroll
    for (int t = 0; t < 16; t++) {
        int k = t * 32 + lane;
        float vs = hs[base + k], ve = he[base + k], vf = hf[base + k], vw = hw[base + k];
        a[0] += vs * Ws[k * 3 + 0]; a[1] += vs * Ws[k * 3 + 1]; a[2] += vs * Ws[k * 3 + 2];
        a[3] += ve * We[k];
        a[4] += vf * Wf[k];
        a[5] += vw * Ww[k * 2 + 0]; a[6] += vw * Ww[k * 2 + 1];
    }
    #pragma unroll
    for (int j = 0; j < 7; j++)
        #pragma unroll
        for (int s = 16; s > 0; s >>= 1)
            a[j] += __shfl_xor_sync(~0u, a[j], s);
    if (lane == 0) {
        float* o = out + (size_t)gw * 7;
        o[0] = a[0] + bs[0]; o[1] = a[1] + bs[1]; o[2] = a[2] + bs[2];
        o[3] = a[3] + be[0];
        o[4] = a[4] + bfv[0];
        o[5] = a[5] + bw[0]; o[6] = a[6] + bw[1];
    }
}

static void gemm(const float* A1, const float* A2, const __half* Bh,
                 int K, const float* bias, int mode,
                 const float* add, const float* mix, float* out) {
    gemm_kernel<<<dim3(4, 256), 256, SMEM_SZ>>>(A1, A2, Bh, K, bias, mode, add, mix, out);
}

extern "C" void kernel_launch(void* const* d_in, const int* in_sizes, int n_in,
                              void* d_out, int out_size) {
    const float* sh = (const float*)d_in[0];
    cudaFuncSetAttribute(gemm_kernel, cudaFuncAttributeMaxDynamicSharedMemorySize, SMEM_SZ);

    __half *wh;
    float *e, *f, *w, *fm, *wm, *h2, *h3;
    cudaGetSymbolAddress((void**)&wh, g_wh);
    cudaGetSymbolAddress((void**)&e,  g_e);
    cudaGetSymbolAddress((void**)&f,  g_f);
    cudaGetSymbolAddress((void**)&w,  g_w);
    cudaGetSymbolAddress((void**)&fm, g_fm);
    cudaGetSymbolAddress((void**)&wm, g_wm);
    cudaGetSymbolAddress((void**)&h2, g_h2);
    cudaGetSymbolAddress((void**)&h3, g_h3);

    const size_t SB = (size_t)BROWS * HDIM * sizeof(float);
    cudaMemcpyAsync(e, d_in[1], SB, cudaMemcpyDeviceToDevice);
    cudaMemcpyAsync(f, d_in[2], SB, cudaMemcpyDeviceToDevice);
    cudaMemcpyAsync(w, d_in[3], SB, cudaMemcpyDeviceToDevice);

    dim3 tb(32, 8);
    prep_kernel<<<dim3(16, 16, 5), tb>>>((const float*)d_in[4],  wh + OFF_S2E, 512);
    prep_kernel<<<dim3(32, 16, 5), tb>>>((const float*)d_in[6],  wh + OFF_TF,  1024);
    prep_kernel<<<dim3(32, 16, 5), tb>>>((const float*)d_in[8],  wh + OFF_FW,  1024);
    prep_kernel<<<dim3(16, 16, 5), tb>>>((const float*)d_in[10], wh + OFF_FG,  512);
    prep_kernel<<<dim3(16, 16, 5), tb>>>((const float*)d_in[12], wh + OFF_WG,  512);
    for (int j = 0; j < 4; j++)
        prep_kernel<<<dim3(16, 16, 1), tb>>>((const float*)d_in[14 + 4 * j],
                                             wh + OFF_HD + j * 262144, 512);

    for (int i = 0; i < 5; i++) {
        const float* s2e_b = (const float*)d_in[5]  + i * 512;
        const float* tf_b  = (const float*)d_in[7]  + i * 512;
        const float* fw_b  = (const float*)d_in[9]  + i * 512;
        const float* fg_b  = (const float*)d_in[11] + i * 512;
        const float* wg_b  = (const float*)d_in[13] + i * 512;
        int o1 = i * 262144, o2 = i * 524288;
        gemm(sh, nullptr, wh + OFF_S2E + o1, 512, s2e_b, 1, e, nullptr, e);
        gemm(sh, e, wh + OFF_TF + o2, 1024, tf_b, 0, nullptr, nullptr, fm);
        gemm(fm, nullptr, wh + OFF_FG + o1, 512, fg_b, 3, f, fm, f);
        gemm(e, f, wh + OFF_FW + o2, 1024, fw_b, 0, nullptr, nullptr, wm);
        gemm(wm, nullptr, wh + OFF_WG + o1, 512, wg_b, 3, w, wm, w);
    }
    gemm(sh, nullptr, wh + OFF_HD + 0 * 262144, 512,
         (const float*)d_in[15], 2, nullptr, nullptr, fm);
    gemm(e, nullptr, wh + OFF_HD + 1 * 262144, 512,
         (const float*)d_in[19], 2, nullptr, nullptr, wm);
    gemm(f, nullptr, wh + OFF_HD + 2 * 262144, 512,
         (const float*)d_in[23], 2, nullptr, nullptr, h2);
    gemm(w, nullptr, wh + OFF_HD + 3 * 262144, 512,
         (const float*)d_in[27], 2, nullptr, nullptr, h3);

    heads_kernel<<<BROWS / 8, 256>>>(
        fm, wm, h2, h3,
        (const float*)d_in[16], (const float*)d_in[17],
        (const float*)d_in[20], (const float*)d_in[21],
        (const float*)d_in[24], (const float*)d_in[25],
        (const float*)d_in[28], (const float*)d_in[29],
        (float*)d_out);
}

// round 12
// speedup vs baseline: 1.8382x; 1.8382x over previous
#include <cuda_runtime.h>
#include <cuda_fp16.h>
#include <cstdint>

#define BROWS 32768
#define HDIM  512

#define OFF_S2E 0
#define OFF_TF  1310720
#define OFF_FW  3932160
#define OFF_FG  6553600
#define OFF_WG  7864320
#define OFF_HD  9175040
#define WT_TOT  10223616

__device__ __half g_wh[WT_TOT];
__device__ float g_e [BROWS*HDIM];
__device__ float g_f [BROWS*HDIM];
__device__ float g_w [BROWS*HDIM];
__device__ float g_fm[BROWS*HDIM];
__device__ float g_wm[BROWS*HDIM];
__device__ float g_h2[BROWS*HDIM];
__device__ float g_h3[BROWS*HDIM];
__device__ __half g_sh16[BROWS*HDIM];
__device__ __half g_e16 [BROWS*HDIM];
__device__ __half g_f16 [BROWS*HDIM];
__device__ __half g_w16 [BROWS*HDIM];
__device__ __half g_fm16[BROWS*HDIM];
__device__ __half g_wm16[BROWS*HDIM];

// ---------------- helpers ----------------
__device__ __forceinline__ uint32_t smem_u32(const void* p) {
    uint32_t a;
    asm("{ .reg .u64 t; cvta.to.shared.u64 t, %1; cvt.u32.u64 %0, t; }" : "=r"(a) : "l"(p));
    return a;
}
__device__ __forceinline__ void cpa16(uint32_t dst, const void* src) {
    asm volatile("cp.async.cg.shared.global [%0], [%1], 16;" :: "r"(dst), "l"(src));
}
#define CP_COMMIT() asm volatile("cp.async.commit_group;" ::: "memory")
#define CP_WAIT2()  asm volatile("cp.async.wait_group 2;" ::: "memory")
#define CP_WAIT1()  asm volatile("cp.async.wait_group 1;" ::: "memory")
#define CP_WAIT0()  asm volatile("cp.async.wait_group 0;" ::: "memory")

#define LDM4(r, addr) \
    asm volatile("ldmatrix.sync.aligned.m8n8.x4.shared.b16 {%0,%1,%2,%3}, [%4];" \
        : "=r"((r)[0]), "=r"((r)[1]), "=r"((r)[2]), "=r"((r)[3]) : "r"(addr))

#define MMA(d, a, b) \
    asm volatile("mma.sync.aligned.m16n8k16.row.col.f32.f16.f16.f32 " \
        "{%0,%1,%2,%3}, {%4,%5,%6,%7}, {%8,%9}, {%0,%1,%2,%3};" \
        : "+f"((d)[0]), "+f"((d)[1]), "+f"((d)[2]), "+f"((d)[3]) \
        : "r"((a)[0]), "r"((a)[1]), "r"((a)[2]), "r"((a)[3]), "r"((b)[0]), "r"((b)[1]))

// transpose [K,512] fp32 -> [512,K] fp16 (layer = blockIdx.z)
__global__ void prep_kernel(const float* src, __half* dh, int K) {
    __shared__ float tile[32][33];
    int z = blockIdx.z;
    src += (size_t)z * K * 512;
    size_t dof = (size_t)z * 512 * K;
    int k0 = blockIdx.x * 32, n0 = blockIdx.y * 32;
    int tx = threadIdx.x, ty = threadIdx.y;
    for (int r = ty; r < 32; r += 8)
        tile[r][tx] = src[(size_t)(k0 + r) * 512 + n0 + tx];
    __syncthreads();
    for (int r = ty; r < 32; r += 8)
        dh[dof + (size_t)(n0 + r) * K + k0 + tx] = __float2half_rn(tile[tx][r]);
}

// fp32 -> fp16 shadow copy (4 elems/thread)
__global__ void cvt_kernel(const float* src, __half* dst) {
    size_t i = ((size_t)blockIdx.x * blockDim.x + threadIdx.x) * 4;
    float4 v = *(const float4*)(src + i);
    __half2 a = __floats2half2_rn(v.x, v.y);
    __half2 b = __floats2half2_rn(v.z, v.w);
    uint2 pk = make_uint2(*(uint32_t*)&a, *(uint32_t*)&b);
    *(uint2*)(dst + i) = pk;
}

// smem: 3-stage x (A 18432B + B 18432B), 144B padded rows, K-chunk 64
#define BBASE 55296
#define SMEM_SZ 110592

// modes: 0 bias  1 bias+add  2 gelu(x+bias)  3 add + sigmoid(x+bias)*(mix-add)
__global__ void __launch_bounds__(256, 2) gemm_kernel(
    const __half* A1, const __half* A2,
    const __half* Bh, int Ktot,
    const float* bias, int mode, const float* add, const float* mix,
    float* out, __half* out16)
{
    extern __shared__ char smem[];
    const uint32_t sb = smem_u32(smem);
    const int tid = threadIdx.x, lane = tid & 31, wid = tid >> 5;
    const int m0 = blockIdx.y * 128, n0 = blockIdx.x * 128;
    const int wm = wid & 3, wn = wid >> 2;
    const int rowT = tid >> 1, segT = tid & 1;

    float acc[2][8][4];
    #pragma unroll
    for (int i = 0; i < 2; i++)
        #pragma unroll
        for (int j = 0; j < 8; j++)
            #pragma unroll
            for (int q = 0; q < 4; q++) acc[i][j][q] = 0.f;

    const int NC = Ktot >> 6;

#define ISSUE(cc) do {                                                             \
    int kg_ = (cc) * 64;                                                           \
    const __half* Ap_ = (kg_ < 512) ? A1 : A2;                                     \
    int kk_ = (kg_ < 512) ? kg_ : kg_ - 512;                                       \
    int buf_ = (cc) % 3;                                                           \
    const __half* as_ = Ap_ + (size_t)(m0 + rowT) * HDIM + kk_ + segT * 32;        \
    uint32_t ad_ = sb + buf_ * 18432 + rowT * 144 + segT * 64;                     \
    cpa16(ad_, as_); cpa16(ad_ + 16, as_ + 8);                                     \
    cpa16(ad_ + 32, as_ + 16); cpa16(ad_ + 48, as_ + 24);                          \
    const __half* bs_ = Bh + (size_t)(n0 + rowT) * Ktot + kg_ + segT * 32;         \
    uint32_t bd_ = sb + BBASE + buf_ * 18432 + rowT * 144 + segT * 64;             \
    cpa16(bd_, bs_); cpa16(bd_ + 16, bs_ + 8);                                     \
    cpa16(bd_ + 32, bs_ + 16); cpa16(bd_ + 48, bs_ + 24);                          \
    CP_COMMIT();                                                                   \
} while (0)

    ISSUE(0);
    if (NC > 1) ISSUE(1);

    // ldmatrix lane addressing (validated fragment scheme)
    const int arow = wm * 32 + (lane & 15);
    const int acolb = ((lane >> 4) & 1) * 16;
    const int g = lane >> 3, lr = lane & 7;
    const int brow = wn * 64 + ((g & 2) ? 8 : 0) + lr;
    const int bcolb = (g & 1) * 16;

    for (int c = 0; c < NC; c++) {
        __syncthreads();   // reads of buffer (c-1)%3 == (c+2)%3 complete everywhere
        if (c + 2 < NC) { ISSUE(c + 2); CP_WAIT2(); }
        else if (c + 1 < NC) CP_WAIT1();
        else CP_WAIT0();
        __syncthreads();   // chunk c data visible to all threads

        const uint32_t abase = sb + (c % 3) * 18432;
        const uint32_t bbase = sb + BBASE + (c % 3) * 18432;
        #pragma unroll
        for (int ks = 0; ks < 4; ks++) {
            uint32_t ah_[2][4];
            #pragma unroll
            for (int i = 0; i < 2; i++)
                LDM4(ah_[i], abase + (uint32_t)((arow + i * 16) * 144 + ks * 32 + acolb));
            #pragma unroll
            for (int jp = 0; jp < 4; jp++) {
                uint32_t bh_[4];
                LDM4(bh_, bbase + (uint32_t)((brow + jp * 16) * 144 + ks * 32 + bcolb));
                #pragma unroll
                for (int i = 0; i < 2; i++) {
                    #pragma unroll
                    for (int jj = 0; jj < 2; jj++)
                        MMA(acc[i][jp * 2 + jj], ah_[i], bh_ + 2 * jj);
                }
            }
        }
    }

    // epilogue: fp32 out + optional fp16 shadow, float2 stores
    const int r0b = m0 + wm * 32 + (lane >> 2);
    const int cb  = n0 + wn * 64 + (lane & 3) * 2;
    const float is2 = 0.7071067811865475f;
    #pragma unroll
    for (int i = 0; i < 2; i++) {
        #pragma unroll
        for (int j = 0; j < 8; j++) {
            int cc = cb + j * 8;
            float b0 = bias[cc], b1 = bias[cc + 1];
            #pragma unroll
            for (int h = 0; h < 2; h++) {
                int rr = r0b + i * 16 + h * 8;
                size_t gix = (size_t)rr * HDIM + cc;
                float v0 = acc[i][j][h * 2 + 0] + b0;
                float v1 = acc[i][j][h * 2 + 1] + b1;
                float2 res;
                if (mode == 0) {
                    res.x = v0; res.y = v1;
                } else if (mode == 1) {
                    float2 ad = *(const float2*)(add + gix);
                    res.x = v0 + ad.x; res.y = v1 + ad.y;
                } else if (mode == 2) {
                    res.x = 0.5f * v0 * (1.f + erff(v0 * is2));
                    res.y = 0.5f * v1 * (1.f + erff(v1 * is2));
                } else {
                    float2 ad = *(const float2*)(add + gix);
                    float2 mx = *(const float2*)(mix + gix);
                    float s0 = 1.f / (1.f + __expf(-v0));
                    float s1 = 1.f / (1.f + __expf(-v1));
                    res.x = ad.x + s0 * (mx.x - ad.x);
                    res.y = ad.y + s1 * (mx.y - ad.y);
                }
                *(float2*)(out + gix) = res;
                if (out16) {
                    __half2 hp = __floats2half2_rn(res.x, res.y);
                    *(__half2*)(out16 + gix) = hp;
                }
            }
        }
    }
}

// tiny second-layer heads: out[B,7]
__global__ void heads_kernel(
    const float* hs, const float* he, const float* hf, const float* hw,
    const float* Ws, const float* bs, const float* We, const float* be,
    const float* Wf, const float* bfv, const float* Ww, const float* bw,
    float* out)
{
    int gw = (int)((blockIdx.x * blockDim.x + threadIdx.x) >> 5);
    int lane = threadIdx.x & 31;
    if (gw >= BROWS) return;
    size_t base = (size_t)gw * HDIM;
    float a[7] = {0, 0, 0, 0, 0, 0, 0};
    #pragma unroll
    for (int t = 0; t < 16; t++) {
        int k = t * 32 + lane;
        float vs = hs[base + k], ve = he[base + k], vf = hf[base + k], vw = hw[base + k];
        a[0] += vs * Ws[k * 3 + 0]; a[1] += vs * Ws[k * 3 + 1]; a[2] += vs * Ws[k * 3 + 2];
        a[3] += ve * We[k];
        a[4] += vf * Wf[k];
        a[5] += vw * Ww[k * 2 + 0]; a[6] += vw * Ww[k * 2 + 1];
    }
    #pragma unroll
    for (int j = 0; j < 7; j++)
        #pragma unroll
        for (int s = 16; s > 0; s >>= 1)
            a[j] += __shfl_xor_sync(~0u, a[j], s);
    if (lane == 0) {
        float* o = out + (size_t)gw * 7;
        o[0] = a[0] + bs[0]; o[1] = a[1] + bs[1]; o[2] = a[2] + bs[2];
        o[3] = a[3] + be[0];
        o[4] = a[4] + bfv[0];
        o[5] = a[5] + bw[0]; o[6] = a[6] + bw[1];
    }
}

static void gemm(const __half* A1, const __half* A2, const __half* Bh,
                 int K, const float* bias, int mode,
                 const float* add, const float* mix, float* out, __half* out16) {
    gemm_kernel<<<dim3(4, 256), 256, SMEM_SZ>>>(A1, A2, Bh, K, bias, mode, add, mix, out, out16);
}

extern "C" void kernel_launch(void* const* d_in, const int* in_sizes, int n_in,
                              void* d_out, int out_size) {
    cudaFuncSetAttribute(gemm_kernel, cudaFuncAttributeMaxDynamicSharedMemorySize, SMEM_SZ);

    __half *wh, *sh16, *e16, *f16, *w16, *fm16, *wm16;
    float *e, *f, *w, *fm, *wm, *h2, *h3;
    cudaGetSymbolAddress((void**)&wh, g_wh);
    cudaGetSymbolAddress((void**)&e,  g_e);
    cudaGetSymbolAddress((void**)&f,  g_f);
    cudaGetSymbolAddress((void**)&w,  g_w);
    cudaGetSymbolAddress((void**)&fm, g_fm);
    cudaGetSymbolAddress((void**)&wm, g_wm);
    cudaGetSymbolAddress((void**)&h2, g_h2);
    cudaGetSymbolAddress((void**)&h3, g_h3);
    cudaGetSymbolAddress((void**)&sh16, g_sh16);
    cudaGetSymbolAddress((void**)&e16,  g_e16);
    cudaGetSymbolAddress((void**)&f16,  g_f16);
    cudaGetSymbolAddress((void**)&w16,  g_w16);
    cudaGetSymbolAddress((void**)&fm16, g_fm16);
    cudaGetSymbolAddress((void**)&wm16, g_wm16);

    const size_t SB = (size_t)BROWS * HDIM * sizeof(float);
    cudaMemcpyAsync(e, d_in[1], SB, cudaMemcpyDeviceToDevice);
    cudaMemcpyAsync(f, d_in[2], SB, cudaMemcpyDeviceToDevice);
    cudaMemcpyAsync(w, d_in[3], SB, cudaMemcpyDeviceToDevice);
    cvt_kernel<<<BROWS * HDIM / 4 / 256, 256>>>((const float*)d_in[0], sh16);

    dim3 tb(32, 8);
    prep_kernel<<<dim3(16, 16, 5), tb>>>((const float*)d_in[4],  wh + OFF_S2E, 512);
    prep_kernel<<<dim3(32, 16, 5), tb>>>((const float*)d_in[6],  wh + OFF_TF,  1024);
    prep_kernel<<<dim3(32, 16, 5), tb>>>((const float*)d_in[8],  wh + OFF_FW,  1024);
    prep_kernel<<<dim3(16, 16, 5), tb>>>((const float*)d_in[10], wh + OFF_FG,  512);
    prep_kernel<<<dim3(16, 16, 5), tb>>>((const float*)d_in[12], wh + OFF_WG,  512);
    for (int j = 0; j < 4; j++)
        prep_kernel<<<dim3(16, 16, 1), tb>>>((const float*)d_in[14 + 4 * j],
                                             wh + OFF_HD + j * 262144, 512);

    for (int i = 0; i < 5; i++) {
        const float* s2e_b = (const float*)d_in[5]  + i * 512;
        const float* tf_b  = (const float*)d_in[7]  + i * 512;
        const float* fw_b  = (const float*)d_in[9]  + i * 512;
        const float* fg_b  = (const float*)d_in[11] + i * 512;
        const float* wg_b  = (const float*)d_in[13] + i * 512;
        int o1 = i * 262144, o2 = i * 524288;
        // e = e + sh@s2e + b        (writes e, e16)
        gemm(sh16, nullptr, wh + OFF_S2E + o1, 512, s2e_b, 1, e, nullptr, e, e16);
        // fm = [sh,e]@tf + b        (writes fm, fm16)
        gemm(sh16, e16, wh + OFF_TF + o2, 1024, tf_b, 0, nullptr, nullptr, fm, fm16);
        // f = f + sig(fm@fg+b)*(fm-f)  (writes f, f16)
        gemm(fm16, nullptr, wh + OFF_FG + o1, 512, fg_b, 3, f, fm, f, f16);
        // wm = [e,f]@fw + b         (writes wm, wm16)
        gemm(e16, f16, wh + OFF_FW + o2, 1024, fw_b, 0, nullptr, nullptr, wm, wm16);
        // w = w + sig(wm@wg+b)*(wm-w)  (writes w, w16)
        gemm(wm16, nullptr, wh + OFF_WG + o1, 512, wg_b, 3, w, wm, w, w16);
    }
    // head hiddens: gelu(x@W1+b1) -> fp32 only
    gemm(sh16, nullptr, wh + OFF_HD + 0 * 262144, 512,
         (const float*)d_in[15], 2, nullptr, nullptr, fm, nullptr);
    gemm(e16, nullptr, wh + OFF_HD + 1 * 262144, 512,
         (const float*)d_in[19], 2, nullptr, nullptr, wm, nullptr);
    gemm(f16, nullptr, wh + OFF_HD + 2 * 262144, 512,
         (const float*)d_in[23], 2, nullptr, nullptr, h2, nullptr);
    gemm(w16, nullptr, wh + OFF_HD + 3 * 262144, 512,
         (const float*)d_in[27], 2, nullptr, nullptr, h3, nullptr);

    heads_kernel<<<BROWS / 8, 256>>>(
        fm, wm, h2, h3,
        (const float*)d_in[16], (const float*)d_in[17],
        (const float*)d_in[20], (const float*)d_in[21],
        (const float*)d_in[24], (const float*)d_in[25],
        (const float*)d_in[28], (const float*)d_in[29],
        (float*)d_out);
}

// round 13
// speedup vs baseline: 1.9432x; 1.0572x over previous
#include <cuda_runtime.h>
#include <cuda_fp16.h>
#include <cstdint>

#define BROWS 32768
#define HDIM  512

#define OFF_S2E 0
#define OFF_TF  1310720
#define OFF_FW  3932160
#define OFF_FG  6553600
#define OFF_WG  7864320
#define OFF_HD  9175040
#define WT_TOT  10223616

__device__ __half g_wh[WT_TOT];
__device__ float g_e [BROWS*HDIM];
__device__ float g_f [BROWS*HDIM];
__device__ float g_w [BROWS*HDIM];
__device__ float g_fm[BROWS*HDIM];
__device__ float g_wm[BROWS*HDIM];
__device__ float g_h2[BROWS*HDIM];
__device__ float g_h3[BROWS*HDIM];
__device__ __half g_sh16[BROWS*HDIM];
__device__ __half g_e16 [BROWS*HDIM];
__device__ __half g_f16 [BROWS*HDIM];
__device__ __half g_w16 [BROWS*HDIM];
__device__ __half g_fm16[BROWS*HDIM];
__device__ __half g_wm16[BROWS*HDIM];

// ---------------- helpers ----------------
__device__ __forceinline__ uint32_t smem_u32(const void* p) {
    uint32_t a;
    asm("{ .reg .u64 t; cvta.to.shared.u64 t, %1; cvt.u32.u64 %0, t; }" : "=r"(a) : "l"(p));
    return a;
}
__device__ __forceinline__ void cpa16(uint32_t dst, const void* src) {
    asm volatile("cp.async.cg.shared.global [%0], [%1], 16;" :: "r"(dst), "l"(src));
}
#define CP_COMMIT() asm volatile("cp.async.commit_group;" ::: "memory")
#define CP_WAIT1()  asm volatile("cp.async.wait_group 1;" ::: "memory")
#define CP_WAIT0()  asm volatile("cp.async.wait_group 0;" ::: "memory")

#define LDM4(r, addr) \
    asm volatile("ldmatrix.sync.aligned.m8n8.x4.shared.b16 {%0,%1,%2,%3}, [%4];" \
        : "=r"((r)[0]), "=r"((r)[1]), "=r"((r)[2]), "=r"((r)[3]) : "r"(addr))

#define MMA(d, a, b) \
    asm volatile("mma.sync.aligned.m16n8k16.row.col.f32.f16.f16.f32 " \
        "{%0,%1,%2,%3}, {%4,%5,%6,%7}, {%8,%9}, {%0,%1,%2,%3};" \
        : "+f"((d)[0]), "+f"((d)[1]), "+f"((d)[2]), "+f"((d)[3]) \
        : "r"((a)[0]), "r"((a)[1]), "r"((a)[2]), "r"((a)[3]), "r"((b)[0]), "r"((b)[1]))

// transpose [K,512] fp32 -> [512,K] fp16 (layer = blockIdx.z)
__global__ void prep_kernel(const float* src, __half* dh, int K) {
    __shared__ float tile[32][33];
    int z = blockIdx.z;
    src += (size_t)z * K * 512;
    size_t dof = (size_t)z * 512 * K;
    int k0 = blockIdx.x * 32, n0 = blockIdx.y * 32;
    int tx = threadIdx.x, ty = threadIdx.y;
    for (int r = ty; r < 32; r += 8)
        tile[r][tx] = src[(size_t)(k0 + r) * 512 + n0 + tx];
    __syncthreads();
    for (int r = ty; r < 32; r += 8)
        dh[dof + (size_t)(n0 + r) * K + k0 + tx] = __float2half_rn(tile[tx][r]);
}

// fp32 -> fp16 shadow copy
__global__ void cvt_kernel(const float* src, __half* dst) {
    size_t i = ((size_t)blockIdx.x * blockDim.x + threadIdx.x) * 4;
    float4 v = *(const float4*)(src + i);
    __half2 a = __floats2half2_rn(v.x, v.y);
    __half2 b = __floats2half2_rn(v.z, v.w);
    *(uint2*)(dst + i) = make_uint2(*(uint32_t*)&a, *(uint32_t*)&b);
}

// smem: 3-stage x (A 18432B + B 18432B), 144B padded rows, K-chunk 64
#define BBASE 55296
#define SMEM_SZ 110592

// shared mainloop: 128x128 tile, K-chunk 64, 3-stage, single barrier/chunk
__device__ __forceinline__ void gemm_core(
    const __half* A1, const __half* A2, const __half* Bh, int Ktot,
    int m0, int n0, const uint32_t sb, int tid, float acc[2][8][4])
{
    const int lane = tid & 31, wid = tid >> 5;
    const int wm = wid & 3, wn = wid >> 2;
    const int rowT = tid >> 1, segT = tid & 1;
    const int NC = Ktot >> 6;

#define ISSUE(cc) do {                                                             \
    int kg_ = (cc) * 64;                                                           \
    const __half* Ap_ = (kg_ < 512) ? A1 : A2;                                     \
    int kk_ = (kg_ < 512) ? kg_ : kg_ - 512;                                       \
    int buf_ = (cc) % 3;                                                           \
    const __half* as_ = Ap_ + (size_t)(m0 + rowT) * HDIM + kk_ + segT * 32;        \
    uint32_t ad_ = sb + buf_ * 18432 + rowT * 144 + segT * 64;                     \
    cpa16(ad_, as_); cpa16(ad_ + 16, as_ + 8);                                     \
    cpa16(ad_ + 32, as_ + 16); cpa16(ad_ + 48, as_ + 24);                          \
    const __half* bs_ = Bh + (size_t)(n0 + rowT) * Ktot + kg_ + segT * 32;         \
    uint32_t bd_ = sb + BBASE + buf_ * 18432 + rowT * 144 + segT * 64;             \
    cpa16(bd_, bs_); cpa16(bd_ + 16, bs_ + 8);                                     \
    cpa16(bd_ + 32, bs_ + 16); cpa16(bd_ + 48, bs_ + 24);                          \
    CP_COMMIT();                                                                   \
} while (0)

    ISSUE(0);
    if (NC > 1) ISSUE(1);

    const int arow = wm * 32 + (lane & 15);
    const int acolb = ((lane >> 4) & 1) * 16;
    const int g = lane >> 3, lr = lane & 7;
    const int brow = wn * 64 + ((g & 2) ? 8 : 0) + lr;
    const int bcolb = (g & 1) * 16;

    for (int c = 0; c < NC; c++) {
        if (c + 1 < NC) CP_WAIT1(); else CP_WAIT0();
        __syncthreads();          // chunk c visible; all threads done reading c-1
        if (c + 2 < NC) ISSUE(c + 2);   // safe: overwrites buf consumed in c-1

        const uint32_t abase = sb + (c % 3) * 18432;
        const uint32_t bbase = sb + BBASE + (c % 3) * 18432;
        #pragma unroll
        for (int ks = 0; ks < 4; ks++) {
            uint32_t ah_[2][4];
            #pragma unroll
            for (int i = 0; i < 2; i++)
                LDM4(ah_[i], abase + (uint32_t)((arow + i * 16) * 144 + ks * 32 + acolb));
            #pragma unroll
            for (int jp = 0; jp < 4; jp++) {
                uint32_t bh_[4];
                LDM4(bh_, bbase + (uint32_t)((brow + jp * 16) * 144 + ks * 32 + bcolb));
                #pragma unroll
                for (int i = 0; i < 2; i++) {
                    #pragma unroll
                    for (int jj = 0; jj < 2; jj++)
                        MMA(acc[i][jp * 2 + jj], ah_[i], bh_ + 2 * jj);
                }
            }
        }
    }
#undef ISSUE
}

// modes: 0 bias  1 bias+add  2 gelu(x+bias)  3 add + sigmoid(x+bias)*(mix16-add)
__global__ void __launch_bounds__(256, 2) gemm_kernel(
    const __half* A1, const __half* A2,
    const __half* Bh, int Ktot,
    const float* bias, int mode, const float* add, const __half* mix16,
    float* out, __half* out16)
{
    extern __shared__ char smem[];
    const uint32_t sb = smem_u32(smem);
    const int tid = threadIdx.x, lane = tid & 31, wid = tid >> 5;
    const int m0 = blockIdx.y * 128, n0 = blockIdx.x * 128;

    float acc[2][8][4];
    #pragma unroll
    for (int i = 0; i < 2; i++)
        #pragma unroll
        for (int j = 0; j < 8; j++)
            #pragma unroll
            for (int q = 0; q < 4; q++) acc[i][j][q] = 0.f;

    gemm_core(A1, A2, Bh, Ktot, m0, n0, sb, tid, acc);

    const int wm = wid & 3, wn = wid >> 2;
    const int r0b = m0 + wm * 32 + (lane >> 2);
    const int cb  = n0 + wn * 64 + (lane & 3) * 2;
    const float is2 = 0.7071067811865475f;
    #pragma unroll
    for (int i = 0; i < 2; i++) {
        #pragma unroll
        for (int j = 0; j < 8; j++) {
            int cc = cb + j * 8;
            float b0 = bias[cc], b1 = bias[cc + 1];
            #pragma unroll
            for (int h = 0; h < 2; h++) {
                int rr = r0b + i * 16 + h * 8;
                size_t gix = (size_t)rr * HDIM + cc;
                float v0 = acc[i][j][h * 2 + 0] + b0;
                float v1 = acc[i][j][h * 2 + 1] + b1;
                float2 res;
                if (mode == 0) {
                    res.x = v0; res.y = v1;
                } else if (mode == 1) {
                    float2 ad = *(const float2*)(add + gix);
                    res.x = v0 + ad.x; res.y = v1 + ad.y;
                } else if (mode == 2) {
                    res.x = 0.5f * v0 * (1.f + erff(v0 * is2));
                    res.y = 0.5f * v1 * (1.f + erff(v1 * is2));
                } else {
                    float2 ad = *(const float2*)(add + gix);
                    __half2 mh = *(const __half2*)(mix16 + gix);
                    float2 mx = __half22float2(mh);
                    float s0 = 1.f / (1.f + __expf(-v0));
                    float s1 = 1.f / (1.f + __expf(-v1));
                    res.x = ad.x + s0 * (mx.x - ad.x);
                    res.y = ad.y + s1 * (mx.y - ad.y);
                }
                if (out) *(float2*)(out + gix) = res;
                if (out16) {
                    __half2 hp = __floats2half2_rn(res.x, res.y);
                    *(__half2*)(out16 + gix) = hp;
                }
            }
        }
    }
}

// fused 4 head-hidden GEMMs: z selects (A, bias, out); gelu epilogue, fp32 out
__global__ void __launch_bounds__(256, 2) head4_kernel(
    const __half* a0, const __half* a1, const __half* a2, const __half* a3,
    const __half* Bh,
    const float* b0p, const float* b1p, const float* b2p, const float* b3p,
    float* o0, float* o1, float* o2, float* o3)
{
    extern __shared__ char smem[];
    const uint32_t sb = smem_u32(smem);
    const int tid = threadIdx.x, lane = tid & 31, wid = tid >> 5;
    const int m0 = blockIdx.y * 128, n0 = blockIdx.x * 128;
    const int z = blockIdx.z;
    const __half* A = (z == 0) ? a0 : (z == 1) ? a1 : (z == 2) ? a2 : a3;
    const float* bias = (z == 0) ? b0p : (z == 1) ? b1p : (z == 2) ? b2p : b3p;
    float* out = (z == 0) ? o0 : (z == 1) ? o1 : (z == 2) ? o2 : o3;
    const __half* B = Bh + (size_t)z * 262144;

    float acc[2][8][4];
    #pragma unroll
    for (int i = 0; i < 2; i++)
        #pragma unroll
        for (int j = 0; j < 8; j++)
            #pragma unroll
            for (int q = 0; q < 4; q++) acc[i][j][q] = 0.f;

    gemm_core(A, nullptr, B, 512, m0, n0, sb, tid, acc);

    const int wm = wid & 3, wn = wid >> 2;
    const int r0b = m0 + wm * 32 + (lane >> 2);
    const int cb  = n0 + wn * 64 + (lane & 3) * 2;
    const float is2 = 0.7071067811865475f;
    #pragma unroll
    for (int i = 0; i < 2; i++) {
        #pragma unroll
        for (int j = 0; j < 8; j++) {
            int cc = cb + j * 8;
            float b0 = bias[cc], b1 = bias[cc + 1];
            #pragma unroll
            for (int h = 0; h < 2; h++) {
                int rr = r0b + i * 16 + h * 8;
                size_t gix = (size_t)rr * HDIM + cc;
                float v0 = acc[i][j][h * 2 + 0] + b0;
                float v1 = acc[i][j][h * 2 + 1] + b1;
                float2 res;
                res.x = 0.5f * v0 * (1.f + erff(v0 * is2));
                res.y = 0.5f * v1 * (1.f + erff(v1 * is2));
                *(float2*)(out + gix) = res;
            }
        }
    }
}

// tiny second-layer heads: out[B,7]
__global__ void heads_kernel(
    const float* hs, const float* he, const float* hf, const float* hw,
    const float* Ws, const float* bs, const float* We, const float* be,
    const float* Wf, const float* bfv, const float* Ww, const float* bw,
    float* out)
{
    int gw = (int)((blockIdx.x * blockDim.x + threadIdx.x) >> 5);
    int lane = threadIdx.x & 31;
    if (gw >= BROWS) return;
    size_t base = (size_t)gw * HDIM;
    float a[7] = {0, 0, 0, 0, 0, 0, 0};
    #pragma unroll
    for (int t = 0; t < 16; t++) {
        int k = t * 32 + lane;
        float vs = hs[base + k], ve = he[base + k], vf = hf[base + k], vw = hw[base + k];
        a[0] += vs * Ws[k * 3 + 0]; a[1] += vs * Ws[k * 3 + 1]; a[2] += vs * Ws[k * 3 + 2];
        a[3] += ve * We[k];
        a[4] += vf * Wf[k];
        a[5] += vw * Ww[k * 2 + 0]; a[6] += vw * Ww[k * 2 + 1];
    }
    #pragma unroll
    for (int j = 0; j < 7; j++)
        #pragma unroll
        for (int s = 16; s > 0; s >>= 1)
            a[j] += __shfl_xor_sync(~0u, a[j], s);
    if (lane == 0) {
        float* o = out + (size_t)gw * 7;
        o[0] = a[0] + bs[0]; o[1] = a[1] + bs[1]; o[2] = a[2] + bs[2];
        o[3] = a[3] + be[0];
        o[4] = a[4] + bfv[0];
        o[5] = a[5] + bw[0]; o[6] = a[6] + bw[1];
    }
}

static void gemm(const __half* A1, const __half* A2, const __half* Bh,
                 int K, const float* bias, int mode,
                 const float* add, const __half* mix16, float* out, __half* out16) {
    gemm_kernel<<<dim3(4, 256), 256, SMEM_SZ>>>(A1, A2, Bh, K, bias, mode, add, mix16, out, out16);
}

extern "C" void kernel_launch(void* const* d_in, const int* in_sizes, int n_in,
                              void* d_out, int out_size) {
    cudaFuncSetAttribute(gemm_kernel, cudaFuncAttributeMaxDynamicSharedMemorySize, SMEM_SZ);
    cudaFuncSetAttribute(head4_kernel, cudaFuncAttributeMaxDynamicSharedMemorySize, SMEM_SZ);

    __half *wh, *sh16, *e16, *f16, *w16, *fm16, *wm16;
    float *e, *f, *w, *fm, *wm, *h2, *h3;
    cudaGetSymbolAddress((void**)&wh, g_wh);
    cudaGetSymbolAddress((void**)&e,  g_e);
    cudaGetSymbolAddress((void**)&f,  g_f);
    cudaGetSymbolAddress((void**)&w,  g_w);
    cudaGetSymbolAddress((void**)&fm, g_fm);
    cudaGetSymbolAddress((void**)&wm, g_wm);
    cudaGetSymbolAddress((void**)&h2, g_h2);
    cudaGetSymbolAddress((void**)&h3, g_h3);
    cudaGetSymbolAddress((void**)&sh16, g_sh16);
    cudaGetSymbolAddress((void**)&e16,  g_e16);
    cudaGetSymbolAddress((void**)&f16,  g_f16);
    cudaGetSymbolAddress((void**)&w16,  g_w16);
    cudaGetSymbolAddress((void**)&fm16, g_fm16);
    cudaGetSymbolAddress((void**)&wm16, g_wm16);

    const size_t SB = (size_t)BROWS * HDIM * sizeof(float);
    cudaMemcpyAsync(e, d_in[1], SB, cudaMemcpyDeviceToDevice);
    cudaMemcpyAsync(f, d_in[2], SB, cudaMemcpyDeviceToDevice);
    cudaMemcpyAsync(w, d_in[3], SB, cudaMemcpyDeviceToDevice);
    cvt_kernel<<<BROWS * HDIM / 4 / 256, 256>>>((const float*)d_in[0], sh16);

    dim3 tb(32, 8);
    prep_kernel<<<dim3(16, 16, 5), tb>>>((const float*)d_in[4],  wh + OFF_S2E, 512);
    prep_kernel<<<dim3(32, 16, 5), tb>>>((const float*)d_in[6],  wh + OFF_TF,  1024);
    prep_kernel<<<dim3(32, 16, 5), tb>>>((const float*)d_in[8],  wh + OFF_FW,  1024);
    prep_kernel<<<dim3(16, 16, 5), tb>>>((const float*)d_in[10], wh + OFF_FG,  512);
    prep_kernel<<<dim3(16, 16, 5), tb>>>((const float*)d_in[12], wh + OFF_WG,  512);
    for (int j = 0; j < 4; j++)
        prep_kernel<<<dim3(16, 16, 1), tb>>>((const float*)d_in[14 + 4 * j],
                                             wh + OFF_HD + j * 262144, 512);

    for (int i = 0; i < 5; i++) {
        const float* s2e_b = (const float*)d_in[5]  + i * 512;
        const float* tf_b  = (const float*)d_in[7]  + i * 512;
        const float* fw_b  = (const float*)d_in[9]  + i * 512;
        const float* fg_b  = (const float*)d_in[11] + i * 512;
        const float* wg_b  = (const float*)d_in[13] + i * 512;
        int o1 = i * 262144, o2 = i * 524288;
        // e = e + sh@s2e + b            (writes e, e16)
        gemm(sh16, nullptr, wh + OFF_S2E + o1, 512, s2e_b, 1, e, nullptr, e, e16);
        // fm = [sh,e]@tf + b            (fp16 shadow only)
        gemm(sh16, e16, wh + OFF_TF + o2, 1024, tf_b, 0, nullptr, nullptr, nullptr, fm16);
        // f = f + sig(fm@fg+b)*(fm16-f) (writes f, f16)
        gemm(fm16, nullptr, wh + OFF_FG + o1, 512, fg_b, 3, f, fm16, f, f16);
        // wm = [e,f]@fw + b             (fp16 shadow only)
        gemm(e16, f16, wh + OFF_FW + o2, 1024, fw_b, 0, nullptr, nullptr, nullptr, wm16);
        // w = w + sig(wm@wg+b)*(wm16-w) (writes w, w16)
        gemm(wm16, nullptr, wh + OFF_WG + o1, 512, wg_b, 3, w, wm16, w, w16);
    }
    // fused head hiddens: gelu(x@W1+b1) for all 4 heads
    head4_kernel<<<dim3(4, 256, 4), 256, SMEM_SZ>>>(
        sh16, e16, f16, w16, wh + OFF_HD,
        (const float*)d_in[15], (const float*)d_in[19],
        (const float*)d_in[23], (const float*)d_in[27],
        fm, wm, h2, h3);

    heads_kernel<<<BROWS / 8, 256>>>(
        fm, wm, h2, h3,
        (const float*)d_in[16], (const float*)d_in[17],
        (const float*)d_in[20], (const float*)d_in[21],
        (const float*)d_in[24], (const float*)d_in[25],
        (const float*)d_in[28], (const float*)d_in[29],
        (float*)d_out);
}